// round 6
// baseline (speedup 1.0000x reference)
#include <cuda_runtime.h>
#include <math.h>

#define N_NODES 20000
#define N_EDGES 320000

// Scratch buffers (max width 640 floats/node). __device__ globals per alloc rules.
__device__ float g_bufA[N_NODES * 640];
__device__ float g_bufB[N_NODES * 640];
__device__ float g_bufC[N_NODES * 640];
__device__ int   g_edge_is64;   // 1 if edge_index is int64, 0 if int32

__device__ __forceinline__ float elu1(float z) { return z > 0.f ? z : expm1f(z); }
// elu(elu(z)): z>0 -> z ; z<=0 -> expm1(expm1(z))   (inner expm1(z) in (-1,0])
__device__ __forceinline__ float elu2(float z) { return z > 0.f ? z : expm1f(expm1f(z)); }

// ---------------------------------------------------------------------------
// Edge-index dtype detection. Reference asks for int64 but stock JAX (x64
// disabled) silently produces int32. Interpreting the first 2048 words as
// int64: true-int64 data is always in [0, N_NODES); int32 data pairs two
// indices per word -> astronomically unlikely to stay in range.
// Recomputed every call (deterministic, capture-safe).
// ---------------------------------------------------------------------------
__global__ void detect_dtype_kernel(const void* __restrict__ edge)
{
    const long long* e64 = (const long long*)edge;
    int bad = 0;
    for (int i = threadIdx.x; i < 2048; i += 256) {
        long long v = e64[i];
        if (v < 0 || v >= N_NODES) bad = 1;
    }
    bad = __syncthreads_or(bad);
    if (threadIdx.x == 0) g_edge_is64 = bad ? 0 : 1;
}

// ---------------------------------------------------------------------------
// Tiled fp32 GEMM:  C[M,N] = act(A[M,K] @ W[K,N] + bias)
// BM=128, BN=64, BK=16, 256 threads, 8x4 per thread.
// Register-prefetch + smem double-buffering: ONE __syncthreads per k-tile.
//   iter t: compute reads smem[cur]; prefetch regs of tile t+1 issued first;
//           reg->smem stores of t+1 go to smem[cur^1] (dead since iter t-1);
//           single barrier rotates buffers.
// K,N multiples of 16/64 at all call sites; M guarded.
// DUAL=true also writes an identical copy to C2 (seeds the aggregation buffer).
// ---------------------------------------------------------------------------
template <int ACT, bool DUAL>
__global__ __launch_bounds__(256) void gemm_bias_act(
    const float* __restrict__ A, const float* __restrict__ W,
    const float* __restrict__ bias, float* __restrict__ C,
    float* __restrict__ C2, int M, int N, int K)
{
    constexpr int BK = 16;
    __shared__ float As[2][BK][132];  // padded rows, transposed A tile
    __shared__ float Bs[2][BK][64];

    const int tid = threadIdx.x;
    const int tx = tid & 15;       // N direction (x4)
    const int ty = tid >> 4;       // M direction (x8)
    const int row0 = blockIdx.y * 128;
    const int col0 = blockIdx.x * 64;

    // Per-thread load assignments (fixed across k):
    //   A tile: 2 float4 loads; row r = (tid+j*256)>>2, kcol = (tid&3)*4
    //   B tile: 1 float4 load; krow = tid>>4, col c = (tid&15)*4
    const int arR[2] = { (tid) >> 2, (tid + 256) >> 2 };
    const int arK    = (tid & 3) * 4;
    const int bK = tid >> 4;
    const int bC = (tid & 15) * 4;

    float acc[8][4] = {};
    float4 aReg[2], bReg;

    // --- prologue: load tile 0 regs, store to smem[0] ---
    #pragma unroll
    for (int j = 0; j < 2; j++) {
        int gr = row0 + arR[j];
        aReg[j] = make_float4(0.f, 0.f, 0.f, 0.f);
        if (gr < M) aReg[j] = *(const float4*)(A + (size_t)gr * K + arK);
    }
    bReg = *(const float4*)(W + (size_t)bK * N + col0 + bC);

    #pragma unroll
    for (int j = 0; j < 2; j++) {
        int r = arR[j];
        As[0][arK + 0][r] = aReg[j].x;
        As[0][arK + 1][r] = aReg[j].y;
        As[0][arK + 2][r] = aReg[j].z;
        As[0][arK + 3][r] = aReg[j].w;
    }
    *(float4*)&Bs[0][bK][bC] = bReg;
    __syncthreads();

    const int T = K / BK;
    int cur = 0;
    for (int t = 0; t < T; t++) {
        // prefetch tile t+1 into registers (global loads overlap compute)
        if (t + 1 < T) {
            int k1 = (t + 1) * BK;
            #pragma unroll
            for (int j = 0; j < 2; j++) {
                int gr = row0 + arR[j];
                aReg[j] = make_float4(0.f, 0.f, 0.f, 0.f);
                if (gr < M) aReg[j] = *(const float4*)(A + (size_t)gr * K + k1 + arK);
            }
            bReg = *(const float4*)(W + (size_t)(k1 + bK) * N + col0 + bC);
        }

        // compute on smem[cur]
        #pragma unroll
        for (int k = 0; k < BK; k++) {
            float a[8], b[4];
            *(float4*)&a[0] = *(const float4*)&As[cur][k][ty * 8];
            *(float4*)&a[4] = *(const float4*)&As[cur][k][ty * 8 + 4];
            *(float4*)&b[0] = *(const float4*)&Bs[cur][k][tx * 4];
            #pragma unroll
            for (int i = 0; i < 8; i++)
                #pragma unroll
                for (int j = 0; j < 4; j++)
                    acc[i][j] += a[i] * b[j];
        }

        // store tile t+1 into the other buffer (dead data), single barrier
        if (t + 1 < T) {
            int nxt = cur ^ 1;
            #pragma unroll
            for (int j = 0; j < 2; j++) {
                int r = arR[j];
                As[nxt][arK + 0][r] = aReg[j].x;
                As[nxt][arK + 1][r] = aReg[j].y;
                As[nxt][arK + 2][r] = aReg[j].z;
                As[nxt][arK + 3][r] = aReg[j].w;
            }
            *(float4*)&Bs[nxt][bK][bC] = bReg;
            __syncthreads();
            cur = nxt;
        }
    }

    float bv[4];
    *(float4*)bv = *(const float4*)(bias + col0 + tx * 4);

    #pragma unroll
    for (int i = 0; i < 8; i++) {
        int gr = row0 + ty * 8 + i;
        if (gr < M) {
            float4 o;
            float* p = (float*)&o;
            #pragma unroll
            for (int j = 0; j < 4; j++) {
                float z = acc[i][j] + bv[j];
                p[j] = (ACT == 2) ? elu2(z) : (ACT == 1 ? elu1(z) : z);
            }
            size_t off = (size_t)gr * N + col0 + tx * 4;
            *(float4*)(C + off) = o;
            if (DUAL) *(float4*)(C2 + off) = o;
        }
    }
}

// ---------------------------------------------------------------------------
// out = in (seeds aggregation buffer with the self term; layer 1 only)
// ---------------------------------------------------------------------------
__global__ void copy_kernel(const float* __restrict__ in, float* __restrict__ out, int n4)
{
    int i = blockIdx.x * blockDim.x + threadIdx.x;
    if (i < n4) ((float4*)out)[i] = ((const float4*)in)[i];
}

// ---------------------------------------------------------------------------
// Flattened scatter-add: out[dst[e], :] += x[src[e], :].
// One thread per (edge, float4-chunk); CHUNKS = dim/4 compile-time.
// red.global.add.v4.f32 (sm_90+): one L2 atomic per 16B instead of per 4B.
// Edge dtype (int64 vs int32) resolved at runtime via g_edge_is64.
// ---------------------------------------------------------------------------
template <int CHUNKS>
__global__ __launch_bounds__(256) void scatter_add_kernel(
    const float* __restrict__ x, float* __restrict__ out,
    const void* __restrict__ edge)
{
    int i = blockIdx.x * blockDim.x + threadIdx.x;
    if (i >= N_EDGES * CHUNKS) return;
    int e = i / CHUNKS;
    int c = (i - e * CHUNKS) * 4;
    int s, d;
    if (g_edge_is64) {
        const long long* ei = (const long long*)edge;
        s = (int)ei[e];
        d = (int)ei[N_EDGES + e];
    } else {
        const int* ei = (const int*)edge;
        s = ei[e];
        d = ei[N_EDGES + e];
    }
    const int dim = CHUNKS * 4;
    float4 v = *(const float4*)(x + (size_t)s * dim + c);
    float* o = out + (size_t)d * dim + c;
    asm volatile("red.global.add.v4.f32 [%0], {%1, %2, %3, %4};"
                 :: "l"(o), "f"(v.x), "f"(v.y), "f"(v.z), "f"(v.w)
                 : "memory");
}

// ---------------------------------------------------------------------------
// launch
// ---------------------------------------------------------------------------
static inline dim3 gemm_grid(int M, int N) { return dim3(N / 64, (M + 127) / 128); }
static inline int  scat_grid(int chunks)   { return (N_EDGES * chunks + 255) / 256; }

extern "C" void kernel_launch(void* const* d_in, const int* in_sizes, int n_in,
                              void* d_out, int out_size)
{
    const float* features = (const float*)d_in[0];
    const void*  edge     = d_in[1];
    const float* w1a = (const float*)d_in[2];
    const float* b1a = (const float*)d_in[3];
    const float* w1b = (const float*)d_in[4];
    const float* b1b = (const float*)d_in[5];
    const float* w2a = (const float*)d_in[6];
    const float* b2a = (const float*)d_in[7];
    const float* w2b = (const float*)d_in[8];
    const float* b2b = (const float*)d_in[9];
    const float* w3a = (const float*)d_in[10];
    const float* b3a = (const float*)d_in[11];
    const float* w3b = (const float*)d_in[12];
    const float* b3b = (const float*)d_in[13];
    const float* wr  = (const float*)d_in[14];
    const float* br  = (const float*)d_in[15];

    float* out_x   = (float*)d_out;                  // (x, res) tuple: x then res
    float* out_res = out_x + (size_t)N_NODES * 256;

    float *bufA, *bufB, *bufC;
    cudaGetSymbolAddress((void**)&bufA, g_bufA);     // address queries; capture-safe
    cudaGetSymbolAddress((void**)&bufB, g_bufB);
    cudaGetSymbolAddress((void**)&bufC, g_bufC);

    // resolve edge-index dtype (int64 vs silently-degraded int32)
    detect_dtype_kernel<<<1, 256>>>(edge);

    // residual branch: res = elu(features @ wr + br)
    gemm_bias_act<1, false><<<gemm_grid(N_NODES, 256), 256>>>(
        features, wr, br, out_res, nullptr, N_NODES, 256, 256);

    // ---- layer 1 (256 -> 640): agg = features + scatter; two linears, outer elu ----
    copy_kernel<<<(N_NODES * 256 / 4 + 255) / 256, 256>>>(features, bufA, N_NODES * 256 / 4);
    scatter_add_kernel<64><<<scat_grid(64), 256>>>(features, bufA, edge);
    gemm_bias_act<1, false><<<gemm_grid(N_NODES, 640), 256>>>(
        bufA, w1a, b1a, bufB, nullptr, N_NODES, 640, 256);
    // x1 -> bufC (gather source) and bufA (aggregation seed)
    gemm_bias_act<2, true><<<gemm_grid(N_NODES, 640), 256>>>(
        bufB, w1b, b1b, bufC, bufA, N_NODES, 640, 640);

    // ---- layer 2 (640 -> 320) ----
    scatter_add_kernel<160><<<scat_grid(160), 256>>>(bufC, bufA, edge);
    gemm_bias_act<1, false><<<gemm_grid(N_NODES, 320), 256>>>(
        bufA, w2a, b2a, bufB, nullptr, N_NODES, 320, 640);
    // x2 -> bufC and bufA
    gemm_bias_act<2, true><<<gemm_grid(N_NODES, 320), 256>>>(
        bufB, w2b, b2b, bufC, bufA, N_NODES, 320, 320);

    // ---- layer 3 (320 -> 256), no outer elu ----
    scatter_add_kernel<80><<<scat_grid(80), 256>>>(bufC, bufA, edge);
    gemm_bias_act<1, false><<<gemm_grid(N_NODES, 256), 256>>>(
        bufA, w3a, b3a, bufB, nullptr, N_NODES, 256, 320);
    gemm_bias_act<1, false><<<gemm_grid(N_NODES, 256), 256>>>(
        bufB, w3b, b3b, out_x, nullptr, N_NODES, 256, 256);
}

// round 9
// speedup vs baseline: 1.6274x; 1.6274x over previous
#include <cuda_runtime.h>
#include <cuda_bf16.h>
#include <math.h>

#define N_NODES 20000
#define N_EDGES 320000

// Scratch buffers (max width 640 floats/node). __device__ globals per alloc rules.
__device__ float g_bufA[N_NODES * 640];
__device__ float g_bufB[N_NODES * 640];
__device__ float g_bufC[N_NODES * 640];
__device__ int   g_edge_is64;   // 1 if edge_index is int64, 0 if int32

__device__ __forceinline__ float elu1(float z) { return z > 0.f ? z : expm1f(z); }
__device__ __forceinline__ float elu2(float z) { return z > 0.f ? z : expm1f(expm1f(z)); }

// ---------------------------------------------------------------------------
// Edge-index dtype detection (int64 vs silently-degraded int32). Recomputed
// every call; deterministic; capture-safe.
// ---------------------------------------------------------------------------
__global__ void detect_dtype_kernel(const void* __restrict__ edge)
{
    const long long* e64 = (const long long*)edge;
    int bad = 0;
    for (int i = threadIdx.x; i < 2048; i += 256) {
        long long v = e64[i];
        if (v < 0 || v >= N_NODES) bad = 1;
    }
    bad = __syncthreads_or(bad);
    if (threadIdx.x == 0) g_edge_is64 = bad ? 0 : 1;
}

// ---------------------------------------------------------------------------
// PTX helpers: ldmatrix + bf16 mma (fp32 accumulate)
// ---------------------------------------------------------------------------
__device__ __forceinline__ unsigned smem_u32(const void* p)
{
    return (unsigned)__cvta_generic_to_shared(p);
}

__device__ __forceinline__ void ldsm_x4(unsigned& r0, unsigned& r1, unsigned& r2,
                                        unsigned& r3, unsigned addr)
{
    asm volatile("ldmatrix.sync.aligned.m8n8.x4.shared.b16 {%0,%1,%2,%3}, [%4];"
                 : "=r"(r0), "=r"(r1), "=r"(r2), "=r"(r3) : "r"(addr));
}

__device__ __forceinline__ void ldsm_x4t(unsigned& r0, unsigned& r1, unsigned& r2,
                                         unsigned& r3, unsigned addr)
{
    asm volatile("ldmatrix.sync.aligned.m8n8.x4.trans.shared.b16 {%0,%1,%2,%3}, [%4];"
                 : "=r"(r0), "=r"(r1), "=r"(r2), "=r"(r3) : "r"(addr));
}

__device__ __forceinline__ void mma16816(float* c, const unsigned* a, const unsigned* b)
{
    asm volatile(
        "mma.sync.aligned.m16n8k16.row.col.f32.bf16.bf16.f32 "
        "{%0,%1,%2,%3}, {%4,%5,%6,%7}, {%8,%9}, {%0,%1,%2,%3};"
        : "+f"(c[0]), "+f"(c[1]), "+f"(c[2]), "+f"(c[3])
        : "r"(a[0]), "r"(a[1]), "r"(a[2]), "r"(a[3]), "r"(b[0]), "r"(b[1]));
}

__device__ __forceinline__ unsigned pack2(__nv_bfloat16 a, __nv_bfloat16 b)
{
    __nv_bfloat162 t; t.x = a; t.y = b;
    return *(unsigned*)&t;
}

// ---------------------------------------------------------------------------
// Tensor-core GEMM with bf16 hi/lo split (3-term):  C = act(A @ W + bias)
//   x = hi + lo (bf16 each);  a*w ~= ah*wh + al*wh + ah*wl   (al*wl ~ 2^-17 dropped)
// BM=128, BN=64, BK=32, 256 threads = 8 warps (4 M x 2 N), warp tile 32x32.
// fp32 global loads; hi/lo conversion fused into the smem store path.
// ---------------------------------------------------------------------------
template <int ACT, bool DUAL>
__global__ __launch_bounds__(256) void gemm_mma(
    const float* __restrict__ A, const float* __restrict__ W,
    const float* __restrict__ bias, float* __restrict__ C,
    float* __restrict__ C2, int M, int N, int K)
{
    constexpr int LDA = 40;  // bf16 elems per A-tile row (32 + 8 pad); 80B, 16B-divisible
    constexpr int LDB = 72;  // bf16 elems per W-tile row (64 + 8 pad); 144B, 16B-divisible
    __shared__ __align__(16) __nv_bfloat16 Ah[128 * LDA], Al[128 * LDA];
    __shared__ __align__(16) __nv_bfloat16 Bh[32 * LDB],  Bl[32 * LDB];

    const int tid  = threadIdx.x;
    const int lane = tid & 31;
    const int warp = tid >> 5;
    const int wm   = warp & 3;       // 4 warps over M (32 rows each)
    const int wn   = warp >> 2;      // 2 warps over N (32 cols each)
    const int row0 = blockIdx.y * 128;
    const int col0 = blockIdx.x * 64;

    float acc[2][4][4];
    #pragma unroll
    for (int i = 0; i < 2; i++)
        #pragma unroll
        for (int j = 0; j < 4; j++)
            #pragma unroll
            for (int l = 0; l < 4; l++) acc[i][j][l] = 0.f;

    for (int k0 = 0; k0 < K; k0 += 32) {
        // ---- load + split A tile: 128x32 fp32 -> Ah/Al bf16 ----
        #pragma unroll
        for (int i = 0; i < 4; i++) {
            int r  = (tid >> 3) + i * 32;
            int kc = (tid & 7) * 4;
            int gr = row0 + r;
            float4 v = make_float4(0.f, 0.f, 0.f, 0.f);
            if (gr < M) v = *(const float4*)(A + (size_t)gr * K + k0 + kc);
            __nv_bfloat16 h0 = __float2bfloat16(v.x), h1 = __float2bfloat16(v.y);
            __nv_bfloat16 h2 = __float2bfloat16(v.z), h3 = __float2bfloat16(v.w);
            __nv_bfloat16 l0 = __float2bfloat16(v.x - __bfloat162float(h0));
            __nv_bfloat16 l1 = __float2bfloat16(v.y - __bfloat162float(h1));
            __nv_bfloat16 l2 = __float2bfloat16(v.z - __bfloat162float(h2));
            __nv_bfloat16 l3 = __float2bfloat16(v.w - __bfloat162float(h3));
            *(unsigned*)(Ah + r * LDA + kc)     = pack2(h0, h1);
            *(unsigned*)(Ah + r * LDA + kc + 2) = pack2(h2, h3);
            *(unsigned*)(Al + r * LDA + kc)     = pack2(l0, l1);
            *(unsigned*)(Al + r * LDA + kc + 2) = pack2(l2, l3);
        }
        // ---- load + split W tile: 32x64 fp32 -> Bh/Bl bf16 ([k][n]) ----
        #pragma unroll
        for (int i = 0; i < 2; i++) {
            int r  = (tid >> 4) + i * 16;
            int nc = (tid & 15) * 4;
            float4 v = *(const float4*)(W + (size_t)(k0 + r) * N + col0 + nc);
            __nv_bfloat16 h0 = __float2bfloat16(v.x), h1 = __float2bfloat16(v.y);
            __nv_bfloat16 h2 = __float2bfloat16(v.z), h3 = __float2bfloat16(v.w);
            __nv_bfloat16 l0 = __float2bfloat16(v.x - __bfloat162float(h0));
            __nv_bfloat16 l1 = __float2bfloat16(v.y - __bfloat162float(h1));
            __nv_bfloat16 l2 = __float2bfloat16(v.z - __bfloat162float(h2));
            __nv_bfloat16 l3 = __float2bfloat16(v.w - __bfloat162float(h3));
            *(unsigned*)(Bh + r * LDB + nc)     = pack2(h0, h1);
            *(unsigned*)(Bh + r * LDB + nc + 2) = pack2(h2, h3);
            *(unsigned*)(Bl + r * LDB + nc)     = pack2(l0, l1);
            *(unsigned*)(Bl + r * LDB + nc + 2) = pack2(l2, l3);
        }
        __syncthreads();

        #pragma unroll
        for (int kt = 0; kt < 2; kt++) {
            unsigned ah[2][4], al[2][4], bh[2][4], bl[2][4];
            // A frags: m16k16 per mi; ldmatrix x4 (row-major)
            #pragma unroll
            for (int mi = 0; mi < 2; mi++) {
                int r = wm * 32 + mi * 16 + (lane & 15);
                int c = kt * 16 + ((lane >> 4) << 3);
                ldsm_x4(ah[mi][0], ah[mi][1], ah[mi][2], ah[mi][3],
                        smem_u32(Ah + r * LDA + c));
                ldsm_x4(al[mi][0], al[mi][1], al[mi][2], al[mi][3],
                        smem_u32(Al + r * LDA + c));
            }
            // B frags: k16n16 per nb; ldmatrix x4 trans ([k][n] row-major)
            #pragma unroll
            for (int nb = 0; nb < 2; nb++) {
                int kk = kt * 16 + (lane & 15);
                int nn = wn * 32 + nb * 16 + ((lane >> 4) << 3);
                ldsm_x4t(bh[nb][0], bh[nb][1], bh[nb][2], bh[nb][3],
                         smem_u32(Bh + kk * LDB + nn));
                ldsm_x4t(bl[nb][0], bl[nb][1], bl[nb][2], bl[nb][3],
                         smem_u32(Bl + kk * LDB + nn));
            }
            // 3-term split MMA
            #pragma unroll
            for (int mi = 0; mi < 2; mi++)
                #pragma unroll
                for (int ni = 0; ni < 4; ni++) {
                    const unsigned* qh = &bh[ni >> 1][(ni & 1) * 2];
                    const unsigned* ql = &bl[ni >> 1][(ni & 1) * 2];
                    mma16816(acc[mi][ni], ah[mi], qh);
                    mma16816(acc[mi][ni], al[mi], qh);
                    mma16816(acc[mi][ni], ah[mi], ql);
                }
        }
        __syncthreads();
    }

    // ---- epilogue: bias + activation, float2 stores ----
    const int gid = lane >> 2, tig = lane & 3;
    #pragma unroll
    for (int ni = 0; ni < 4; ni++) {
        int cn = col0 + wn * 32 + ni * 8 + tig * 2;
        float2 bv = *(const float2*)(bias + cn);
        #pragma unroll
        for (int mi = 0; mi < 2; mi++) {
            #pragma unroll
            for (int h = 0; h < 2; h++) {
                int gr = row0 + wm * 32 + mi * 16 + gid + h * 8;
                if (gr < M) {
                    float z0 = acc[mi][ni][h * 2 + 0] + bv.x;
                    float z1 = acc[mi][ni][h * 2 + 1] + bv.y;
                    float2 o;
                    o.x = (ACT == 2) ? elu2(z0) : (ACT == 1 ? elu1(z0) : z0);
                    o.y = (ACT == 2) ? elu2(z1) : (ACT == 1 ? elu1(z1) : z1);
                    size_t off = (size_t)gr * N + cn;
                    *(float2*)(C + off) = o;
                    if (DUAL) *(float2*)(C2 + off) = o;
                }
            }
        }
    }
}

// ---------------------------------------------------------------------------
// out = in (seeds aggregation buffer with the self term; layer 1 only)
// ---------------------------------------------------------------------------
__global__ void copy_kernel(const float* __restrict__ in, float* __restrict__ out, int n4)
{
    int i = blockIdx.x * blockDim.x + threadIdx.x;
    if (i < n4) ((float4*)out)[i] = ((const float4*)in)[i];
}

// ---------------------------------------------------------------------------
// Flattened scatter-add: out[dst[e], :] += x[src[e], :].
// One thread per (edge, float4-chunk); red.global.add.v4.f32.
// ---------------------------------------------------------------------------
template <int CHUNKS>
__global__ __launch_bounds__(256) void scatter_add_kernel(
    const float* __restrict__ x, float* __restrict__ out,
    const void* __restrict__ edge)
{
    int i = blockIdx.x * blockDim.x + threadIdx.x;
    if (i >= N_EDGES * CHUNKS) return;
    int e = i / CHUNKS;
    int c = (i - e * CHUNKS) * 4;
    int s, d;
    if (g_edge_is64) {
        const long long* ei = (const long long*)edge;
        s = (int)ei[e];
        d = (int)ei[N_EDGES + e];
    } else {
        const int* ei = (const int*)edge;
        s = ei[e];
        d = ei[N_EDGES + e];
    }
    const int dim = CHUNKS * 4;
    float4 v = *(const float4*)(x + (size_t)s * dim + c);
    float* o = out + (size_t)d * dim + c;
    asm volatile("red.global.add.v4.f32 [%0], {%1, %2, %3, %4};"
                 :: "l"(o), "f"(v.x), "f"(v.y), "f"(v.z), "f"(v.w)
                 : "memory");
}

// ---------------------------------------------------------------------------
// launch
// ---------------------------------------------------------------------------
static inline dim3 gemm_grid(int M, int N) { return dim3(N / 64, (M + 127) / 128); }
static inline int  scat_grid(int chunks)   { return (N_EDGES * chunks + 255) / 256; }

extern "C" void kernel_launch(void* const* d_in, const int* in_sizes, int n_in,
                              void* d_out, int out_size)
{
    const float* features = (const float*)d_in[0];
    const void*  edge     = d_in[1];
    const float* w1a = (const float*)d_in[2];
    const float* b1a = (const float*)d_in[3];
    const float* w1b = (const float*)d_in[4];
    const float* b1b = (const float*)d_in[5];
    const float* w2a = (const float*)d_in[6];
    const float* b2a = (const float*)d_in[7];
    const float* w2b = (const float*)d_in[8];
    const float* b2b = (const float*)d_in[9];
    const float* w3a = (const float*)d_in[10];
    const float* b3a = (const float*)d_in[11];
    const float* w3b = (const float*)d_in[12];
    const float* b3b = (const float*)d_in[13];
    const float* wr  = (const float*)d_in[14];
    const float* br  = (const float*)d_in[15];

    float* out_x   = (float*)d_out;                  // (x, res) tuple: x then res
    float* out_res = out_x + (size_t)N_NODES * 256;

    float *bufA, *bufB, *bufC;
    cudaGetSymbolAddress((void**)&bufA, g_bufA);
    cudaGetSymbolAddress((void**)&bufB, g_bufB);
    cudaGetSymbolAddress((void**)&bufC, g_bufC);

    detect_dtype_kernel<<<1, 256>>>(edge);

    // residual branch: res = elu(features @ wr + br)
    gemm_mma<1, false><<<gemm_grid(N_NODES, 256), 256>>>(
        features, wr, br, out_res, nullptr, N_NODES, 256, 256);

    // ---- layer 1 (256 -> 640) ----
    copy_kernel<<<(N_NODES * 256 / 4 + 255) / 256, 256>>>(features, bufA, N_NODES * 256 / 4);
    scatter_add_kernel<64><<<scat_grid(64), 256>>>(features, bufA, edge);
    gemm_mma<1, false><<<gemm_grid(N_NODES, 640), 256>>>(
        bufA, w1a, b1a, bufB, nullptr, N_NODES, 640, 256);
    gemm_mma<2, true><<<gemm_grid(N_NODES, 640), 256>>>(
        bufB, w1b, b1b, bufC, bufA, N_NODES, 640, 640);

    // ---- layer 2 (640 -> 320) ----
    scatter_add_kernel<160><<<scat_grid(160), 256>>>(bufC, bufA, edge);
    gemm_mma<1, false><<<gemm_grid(N_NODES, 320), 256>>>(
        bufA, w2a, b2a, bufB, nullptr, N_NODES, 320, 640);
    gemm_mma<2, true><<<gemm_grid(N_NODES, 320), 256>>>(
        bufB, w2b, b2b, bufC, bufA, N_NODES, 320, 320);

    // ---- layer 3 (320 -> 256), no outer elu ----
    scatter_add_kernel<80><<<scat_grid(80), 256>>>(bufC, bufA, edge);
    gemm_mma<1, false><<<gemm_grid(N_NODES, 256), 256>>>(
        bufA, w3a, b3a, bufB, nullptr, N_NODES, 256, 320);
    gemm_mma<1, false><<<gemm_grid(N_NODES, 256), 256>>>(
        bufB, w3b, b3b, out_x, nullptr, N_NODES, 256, 256);
}

// round 10
// speedup vs baseline: 1.7809x; 1.0943x over previous
#include <cuda_runtime.h>
#include <cuda_bf16.h>
#include <math.h>

#define N_NODES 20000
#define N_EDGES 320000

// ---- device-global scratch (no allocs allowed) ----
__device__ float g_bufA[N_NODES * 640];          // fp32 aggregation target / seed
__device__ float g_bufC[N_NODES * 640];          // fp32 gather source (x)
__device__ __nv_bfloat16 g_fhi[N_NODES * 256],  g_flo[N_NODES * 256];
__device__ __nv_bfloat16 g_ahi[N_NODES * 640],  g_alo[N_NODES * 640];
__device__ __nv_bfloat16 g_hhi[N_NODES * 640],  g_hlo[N_NODES * 640];
#define W_TOTAL 1093632
__device__ __nv_bfloat16 g_whi[W_TOTAL], g_wlo[W_TOTAL];
__device__ int g_edge_is64;

// weight offsets inside g_whi/g_wlo
#define OFF_W1A 0
#define OFF_W1B 163840
#define OFF_W2A 573440
#define OFF_W2B 778240
#define OFF_W3A 880640
#define OFF_W3B 962560
#define OFF_WR  1028096

__device__ __forceinline__ float elu1(float z) { return z > 0.f ? z : expm1f(z); }
__device__ __forceinline__ float elu2(float z) { return z > 0.f ? z : expm1f(expm1f(z)); }

// ---------------------------------------------------------------------------
__global__ void detect_dtype_kernel(const void* __restrict__ edge)
{
    const long long* e64 = (const long long*)edge;
    int bad = 0;
    for (int i = threadIdx.x; i < 2048; i += 256) {
        long long v = e64[i];
        if (v < 0 || v >= N_NODES) bad = 1;
    }
    bad = __syncthreads_or(bad);
    if (threadIdx.x == 0) g_edge_is64 = bad ? 0 : 1;
}

// ---------------------------------------------------------------------------
// fp32 -> bf16 hi/lo split (vectorized)
// ---------------------------------------------------------------------------
__device__ __forceinline__ unsigned pack2(__nv_bfloat16 a, __nv_bfloat16 b)
{
    __nv_bfloat162 t; t.x = a; t.y = b;
    return *(unsigned*)&t;
}

__global__ void split_kernel(const float* __restrict__ x,
                             __nv_bfloat16* __restrict__ hi,
                             __nv_bfloat16* __restrict__ lo, int n)
{
    int i = (blockIdx.x * blockDim.x + threadIdx.x) * 4;
    if (i >= n) return;
    float4 v = *(const float4*)(x + i);
    __nv_bfloat16 h0 = __float2bfloat16(v.x), h1 = __float2bfloat16(v.y);
    __nv_bfloat16 h2 = __float2bfloat16(v.z), h3 = __float2bfloat16(v.w);
    __nv_bfloat16 l0 = __float2bfloat16(v.x - __bfloat162float(h0));
    __nv_bfloat16 l1 = __float2bfloat16(v.y - __bfloat162float(h1));
    __nv_bfloat16 l2 = __float2bfloat16(v.z - __bfloat162float(h2));
    __nv_bfloat16 l3 = __float2bfloat16(v.w - __bfloat162float(h3));
    *(unsigned*)(hi + i)     = pack2(h0, h1);
    *(unsigned*)(hi + i + 2) = pack2(h2, h3);
    *(unsigned*)(lo + i)     = pack2(l0, l1);
    *(unsigned*)(lo + i + 2) = pack2(l2, l3);
}

// ---------------------------------------------------------------------------
// PTX helpers
// ---------------------------------------------------------------------------
__device__ __forceinline__ unsigned smem_u32(const void* p)
{
    return (unsigned)__cvta_generic_to_shared(p);
}

__device__ __forceinline__ void cp16(unsigned s, const void* g, int zf)
{
    asm volatile("cp.async.cg.shared.global [%0], [%1], 16, %2;"
                 :: "r"(s), "l"(g), "r"(zf) : "memory");
}

__device__ __forceinline__ void ldsm_x4(unsigned& r0, unsigned& r1, unsigned& r2,
                                        unsigned& r3, unsigned addr)
{
    asm volatile("ldmatrix.sync.aligned.m8n8.x4.shared.b16 {%0,%1,%2,%3}, [%4];"
                 : "=r"(r0), "=r"(r1), "=r"(r2), "=r"(r3) : "r"(addr));
}

__device__ __forceinline__ void ldsm_x4t(unsigned& r0, unsigned& r1, unsigned& r2,
                                         unsigned& r3, unsigned addr)
{
    asm volatile("ldmatrix.sync.aligned.m8n8.x4.trans.shared.b16 {%0,%1,%2,%3}, [%4];"
                 : "=r"(r0), "=r"(r1), "=r"(r2), "=r"(r3) : "r"(addr));
}

__device__ __forceinline__ void mma16816(float* c, const unsigned* a, const unsigned* b)
{
    asm volatile(
        "mma.sync.aligned.m16n8k16.row.col.f32.bf16.bf16.f32 "
        "{%0,%1,%2,%3}, {%4,%5,%6,%7}, {%8,%9}, {%0,%1,%2,%3};"
        : "+f"(c[0]), "+f"(c[1]), "+f"(c[2]), "+f"(c[3])
        : "r"(a[0]), "r"(a[1]), "r"(a[2]), "r"(a[3]), "r"(b[0]), "r"(b[1]));
}

// ---------------------------------------------------------------------------
// bf16 hi/lo tensor-core GEMM, cp.async 2-stage pipeline, XOR-swizzled smem.
// BM=128, BN=64, BK=32, 256 thr = 8 warps (4M x 2N), warp tile 32x32.
//   A tile 128x32 (row 64B = 4 chunks), phys chunk = c ^ ((row>>1)&3)
//   B tile 32x64  (row 128B = 8 chunks), phys chunk = c ^ (row&7)
// OUT: 0 = fp32 C;  1 = fp32 C + C2;  2 = bf16 hi/lo split
// ---------------------------------------------------------------------------
template <int ACT, int OUT>
__global__ __launch_bounds__(256) void gemm_mma_bf16(
    const __nv_bfloat16* __restrict__ Ahi, const __nv_bfloat16* __restrict__ Alo,
    const __nv_bfloat16* __restrict__ Whi, const __nv_bfloat16* __restrict__ Wlo,
    const float* __restrict__ bias,
    float* __restrict__ C, float* __restrict__ C2,
    __nv_bfloat16* __restrict__ Chi, __nv_bfloat16* __restrict__ Clo,
    int M, int N, int K)
{
    __shared__ __align__(16) __nv_bfloat16 sAh[2][128 * 32], sAl[2][128 * 32];
    __shared__ __align__(16) __nv_bfloat16 sBh[2][32 * 64],  sBl[2][32 * 64];

    const int tid = threadIdx.x, lane = tid & 31, warp = tid >> 5;
    const int wm = warp & 3, wn = warp >> 2;
    const int row0 = blockIdx.y * 128, col0 = blockIdx.x * 64;
    const int T = K / 32;

    float acc[2][4][4];
    #pragma unroll
    for (int i = 0; i < 2; i++)
        #pragma unroll
        for (int j = 0; j < 4; j++)
            #pragma unroll
            for (int l = 0; l < 4; l++) acc[i][j][l] = 0.f;

    // ---- async issue of tile t into stage buf ----
    auto issue = [&](int t, int buf) {
        int k0 = t * 32;
        #pragma unroll
        for (int it = 0; it < 2; it++) {
            int id = tid + it * 256;          // 512 chunks: r = id>>2, c = id&3
            int r = id >> 2, c = id & 3;
            int gr = row0 + r;
            int pc = c ^ ((r >> 1) & 3);
            int zf = (gr < M) ? 16 : 0;
            const __nv_bfloat16* gh = Ahi + (size_t)gr * K + k0 + c * 8;
            const __nv_bfloat16* gl = Alo + (size_t)gr * K + k0 + c * 8;
            cp16(smem_u32(&sAh[buf][r * 32 + pc * 8]), gh, zf);
            cp16(smem_u32(&sAl[buf][r * 32 + pc * 8]), gl, zf);
        }
        {
            int r = tid >> 3, c = tid & 7;    // 256 chunks
            int pc = c ^ (r & 7);
            const __nv_bfloat16* gh = Whi + (size_t)(k0 + r) * N + col0 + c * 8;
            const __nv_bfloat16* gl = Wlo + (size_t)(k0 + r) * N + col0 + c * 8;
            cp16(smem_u32(&sBh[buf][r * 64 + pc * 8]), gh, 16);
            cp16(smem_u32(&sBl[buf][r * 64 + pc * 8]), gl, 16);
        }
    };

    issue(0, 0);
    asm volatile("cp.async.commit_group;" ::: "memory");

    for (int t = 0; t < T; t++) {
        int buf = t & 1;
        if (t + 1 < T) issue(t + 1, buf ^ 1);
        asm volatile("cp.async.commit_group;" ::: "memory");  // possibly empty group
        asm volatile("cp.async.wait_group 1;" ::: "memory");  // tile t resident
        __syncthreads();

        #pragma unroll
        for (int kt = 0; kt < 2; kt++) {
            unsigned ah[2][4], al[2][4], bh[2][4], bl[2][4];
            #pragma unroll
            for (int mi = 0; mi < 2; mi++) {
                int rr = wm * 32 + mi * 16 + (lane & 15);
                int cc = kt * 2 + (lane >> 4);
                int pc = cc ^ ((rr >> 1) & 3);
                ldsm_x4(ah[mi][0], ah[mi][1], ah[mi][2], ah[mi][3],
                        smem_u32(&sAh[buf][rr * 32 + pc * 8]));
                ldsm_x4(al[mi][0], al[mi][1], al[mi][2], al[mi][3],
                        smem_u32(&sAl[buf][rr * 32 + pc * 8]));
            }
            #pragma unroll
            for (int nb = 0; nb < 2; nb++) {
                int kk = kt * 16 + (lane & 15);
                int cc = wn * 4 + nb * 2 + (lane >> 4);
                int pc = cc ^ (kk & 7);
                ldsm_x4t(bh[nb][0], bh[nb][1], bh[nb][2], bh[nb][3],
                         smem_u32(&sBh[buf][kk * 64 + pc * 8]));
                ldsm_x4t(bl[nb][0], bl[nb][1], bl[nb][2], bl[nb][3],
                         smem_u32(&sBl[buf][kk * 64 + pc * 8]));
            }
            #pragma unroll
            for (int mi = 0; mi < 2; mi++)
                #pragma unroll
                for (int ni = 0; ni < 4; ni++) {
                    const unsigned* qh = &bh[ni >> 1][(ni & 1) * 2];
                    const unsigned* ql = &bl[ni >> 1][(ni & 1) * 2];
                    mma16816(acc[mi][ni], ah[mi], qh);
                    mma16816(acc[mi][ni], al[mi], qh);
                    mma16816(acc[mi][ni], ah[mi], ql);
                }
        }
        __syncthreads();
    }

    // ---- epilogue ----
    const int gid = lane >> 2, tig = lane & 3;
    #pragma unroll
    for (int ni = 0; ni < 4; ni++) {
        int cn = col0 + wn * 32 + ni * 8 + tig * 2;
        float2 bv = *(const float2*)(bias + cn);
        #pragma unroll
        for (int mi = 0; mi < 2; mi++) {
            #pragma unroll
            for (int h = 0; h < 2; h++) {
                int gr = row0 + wm * 32 + mi * 16 + gid + h * 8;
                if (gr < M) {
                    float z0 = acc[mi][ni][h * 2 + 0] + bv.x;
                    float z1 = acc[mi][ni][h * 2 + 1] + bv.y;
                    float o0 = (ACT == 2) ? elu2(z0) : (ACT == 1 ? elu1(z0) : z0);
                    float o1 = (ACT == 2) ? elu2(z1) : (ACT == 1 ? elu1(z1) : z1);
                    size_t off = (size_t)gr * N + cn;
                    if (OUT == 2) {
                        __nv_bfloat16 h0 = __float2bfloat16(o0);
                        __nv_bfloat16 h1 = __float2bfloat16(o1);
                        __nv_bfloat16 l0 = __float2bfloat16(o0 - __bfloat162float(h0));
                        __nv_bfloat16 l1 = __float2bfloat16(o1 - __bfloat162float(h1));
                        *(unsigned*)(Chi + off) = pack2(h0, h1);
                        *(unsigned*)(Clo + off) = pack2(l0, l1);
                    } else {
                        float2 o; o.x = o0; o.y = o1;
                        *(float2*)(C + off) = o;
                        if (OUT == 1) *(float2*)(C2 + off) = o;
                    }
                }
            }
        }
    }
}

// ---------------------------------------------------------------------------
__global__ void copy_kernel(const float* __restrict__ in, float* __restrict__ out, int n4)
{
    int i = blockIdx.x * blockDim.x + threadIdx.x;
    if (i < n4) ((float4*)out)[i] = ((const float4*)in)[i];
}

template <int CHUNKS>
__global__ __launch_bounds__(256) void scatter_add_kernel(
    const float* __restrict__ x, float* __restrict__ out,
    const void* __restrict__ edge)
{
    int i = blockIdx.x * blockDim.x + threadIdx.x;
    if (i >= N_EDGES * CHUNKS) return;
    int e = i / CHUNKS;
    int c = (i - e * CHUNKS) * 4;
    int s, d;
    if (g_edge_is64) {
        const long long* ei = (const long long*)edge;
        s = (int)ei[e];
        d = (int)ei[N_EDGES + e];
    } else {
        const int* ei = (const int*)edge;
        s = ei[e];
        d = ei[N_EDGES + e];
    }
    const int dim = CHUNKS * 4;
    float4 v = *(const float4*)(x + (size_t)s * dim + c);
    float* o = out + (size_t)d * dim + c;
    asm volatile("red.global.add.v4.f32 [%0], {%1, %2, %3, %4};"
                 :: "l"(o), "f"(v.x), "f"(v.y), "f"(v.z), "f"(v.w)
                 : "memory");
}

// ---------------------------------------------------------------------------
static inline dim3 gemm_grid(int M, int N) { return dim3(N / 64, (M + 127) / 128); }
static inline int  scat_grid(int chunks)   { return (N_EDGES * chunks + 255) / 256; }
static inline int  split_grid(int n)       { return (n / 4 + 255) / 256; }

extern "C" void kernel_launch(void* const* d_in, const int* in_sizes, int n_in,
                              void* d_out, int out_size)
{
    const float* features = (const float*)d_in[0];
    const void*  edge     = d_in[1];
    const float* w1a = (const float*)d_in[2];
    const float* b1a = (const float*)d_in[3];
    const float* w1b = (const float*)d_in[4];
    const float* b1b = (const float*)d_in[5];
    const float* w2a = (const float*)d_in[6];
    const float* b2a = (const float*)d_in[7];
    const float* w2b = (const float*)d_in[8];
    const float* b2b = (const float*)d_in[9];
    const float* w3a = (const float*)d_in[10];
    const float* b3a = (const float*)d_in[11];
    const float* w3b = (const float*)d_in[12];
    const float* b3b = (const float*)d_in[13];
    const float* wr  = (const float*)d_in[14];
    const float* br  = (const float*)d_in[15];

    float* out_x   = (float*)d_out;
    float* out_res = out_x + (size_t)N_NODES * 256;

    float *bufA, *bufC;
    __nv_bfloat16 *fhi, *flo, *ahi, *alo, *hhi, *hlo, *whi, *wlo;
    cudaGetSymbolAddress((void**)&bufA, g_bufA);
    cudaGetSymbolAddress((void**)&bufC, g_bufC);
    cudaGetSymbolAddress((void**)&fhi, g_fhi);
    cudaGetSymbolAddress((void**)&flo, g_flo);
    cudaGetSymbolAddress((void**)&ahi, g_ahi);
    cudaGetSymbolAddress((void**)&alo, g_alo);
    cudaGetSymbolAddress((void**)&hhi, g_hhi);
    cudaGetSymbolAddress((void**)&hlo, g_hlo);
    cudaGetSymbolAddress((void**)&whi, g_whi);
    cudaGetSymbolAddress((void**)&wlo, g_wlo);

    detect_dtype_kernel<<<1, 256>>>(edge);

    // weight + feature splits
    split_kernel<<<split_grid(256 * 640), 256>>>(w1a, whi + OFF_W1A, wlo + OFF_W1A, 256 * 640);
    split_kernel<<<split_grid(640 * 640), 256>>>(w1b, whi + OFF_W1B, wlo + OFF_W1B, 640 * 640);
    split_kernel<<<split_grid(640 * 320), 256>>>(w2a, whi + OFF_W2A, wlo + OFF_W2A, 640 * 320);
    split_kernel<<<split_grid(320 * 320), 256>>>(w2b, whi + OFF_W2B, wlo + OFF_W2B, 320 * 320);
    split_kernel<<<split_grid(320 * 256), 256>>>(w3a, whi + OFF_W3A, wlo + OFF_W3A, 320 * 256);
    split_kernel<<<split_grid(256 * 256), 256>>>(w3b, whi + OFF_W3B, wlo + OFF_W3B, 256 * 256);
    split_kernel<<<split_grid(256 * 256), 256>>>(wr,  whi + OFF_WR,  wlo + OFF_WR,  256 * 256);
    split_kernel<<<split_grid(N_NODES * 256), 256>>>(features, fhi, flo, N_NODES * 256);

    // residual: res = elu(features @ wr + br)
    gemm_mma_bf16<1, 0><<<gemm_grid(N_NODES, 256), 256>>>(
        fhi, flo, whi + OFF_WR, wlo + OFF_WR, br,
        out_res, nullptr, nullptr, nullptr, N_NODES, 256, 256);

    // ---- layer 1 (256 -> 640) ----
    copy_kernel<<<(N_NODES * 256 / 4 + 255) / 256, 256>>>(features, bufA, N_NODES * 256 / 4);
    scatter_add_kernel<64><<<scat_grid(64), 256>>>(features, bufA, edge);
    split_kernel<<<split_grid(N_NODES * 256), 256>>>(bufA, ahi, alo, N_NODES * 256);
    gemm_mma_bf16<1, 2><<<gemm_grid(N_NODES, 640), 256>>>(
        ahi, alo, whi + OFF_W1A, wlo + OFF_W1A, b1a,
        nullptr, nullptr, hhi, hlo, N_NODES, 640, 256);
    gemm_mma_bf16<2, 1><<<gemm_grid(N_NODES, 640), 256>>>(
        hhi, hlo, whi + OFF_W1B, wlo + OFF_W1B, b1b,
        bufC, bufA, nullptr, nullptr, N_NODES, 640, 640);

    // ---- layer 2 (640 -> 320) ----
    scatter_add_kernel<160><<<scat_grid(160), 256>>>(bufC, bufA, edge);
    split_kernel<<<split_grid(N_NODES * 640), 256>>>(bufA, ahi, alo, N_NODES * 640);
    gemm_mma_bf16<1, 2><<<gemm_grid(N_NODES, 320), 256>>>(
        ahi, alo, whi + OFF_W2A, wlo + OFF_W2A, b2a,
        nullptr, nullptr, hhi, hlo, N_NODES, 320, 640);
    gemm_mma_bf16<2, 1><<<gemm_grid(N_NODES, 320), 256>>>(
        hhi, hlo, whi + OFF_W2B, wlo + OFF_W2B, b2b,
        bufC, bufA, nullptr, nullptr, N_NODES, 320, 320);

    // ---- layer 3 (320 -> 256), no outer elu ----
    scatter_add_kernel<80><<<scat_grid(80), 256>>>(bufC, bufA, edge);
    split_kernel<<<split_grid(N_NODES * 320), 256>>>(bufA, ahi, alo, N_NODES * 320);
    gemm_mma_bf16<1, 2><<<gemm_grid(N_NODES, 256), 256>>>(
        ahi, alo, whi + OFF_W3A, wlo + OFF_W3A, b3a,
        nullptr, nullptr, hhi, hlo, N_NODES, 256, 320);
    gemm_mma_bf16<1, 0><<<gemm_grid(N_NODES, 256), 256>>>(
        hhi, hlo, whi + OFF_W3B, wlo + OFF_W3B, b3b,
        out_x, nullptr, nullptr, nullptr, N_NODES, 256, 256);
}

// round 14
// speedup vs baseline: 2.4028x; 1.3492x over previous
#include <cuda_runtime.h>
#include <cuda_bf16.h>
#include <math.h>

#define N_NODES 20000
#define N_EDGES 320000
#define SCAN_NB 79   // ceil(20000/256)

// ---- device-global scratch (no allocs allowed) ----
__device__ __nv_bfloat16 g_fhi[N_NODES * 256], g_flo[N_NODES * 256];
__device__ __nv_bfloat16 g_ahi[N_NODES * 640], g_alo[N_NODES * 640];
__device__ __nv_bfloat16 g_hhi[N_NODES * 640], g_hlo[N_NODES * 640];
__device__ __nv_bfloat16 g_xhi[N_NODES * 640], g_xlo[N_NODES * 640];
#define W_TOTAL 1093632
__device__ __nv_bfloat16 g_whi[W_TOTAL], g_wlo[W_TOTAL];
__device__ int g_edge_is64;
// CSR scratch
__device__ int g_deg[N_NODES];
__device__ int g_incl[N_NODES];
__device__ int g_part[128];
__device__ int g_partoff[128];
__device__ int g_off[N_NODES + 1];
__device__ int g_cur[N_NODES];
__device__ int g_csrc[N_EDGES];

// weight offsets inside g_whi/g_wlo
#define OFF_W1A 0
#define OFF_W1B 163840
#define OFF_W2A 573440
#define OFF_W2B 778240
#define OFF_W3A 880640
#define OFF_W3B 962560
#define OFF_WR  1028096

__device__ __forceinline__ float elu1(float z) { return z > 0.f ? z : expm1f(z); }
__device__ __forceinline__ float elu2(float z) { return z > 0.f ? z : expm1f(expm1f(z)); }

__device__ __forceinline__ unsigned pack2(__nv_bfloat16 a, __nv_bfloat16 b)
{
    __nv_bfloat162 t; t.x = a; t.y = b;
    return *(unsigned*)&t;
}

// ---------------------------------------------------------------------------
__global__ void detect_dtype_kernel(const void* __restrict__ edge)
{
    const long long* e64 = (const long long*)edge;
    int bad = 0;
    for (int i = threadIdx.x; i < 2048; i += 256) {
        long long v = e64[i];
        if (v < 0 || v >= N_NODES) bad = 1;
    }
    bad = __syncthreads_or(bad);
    if (threadIdx.x == 0) g_edge_is64 = bad ? 0 : 1;
}

__device__ __forceinline__ int edge_at(const void* edge, int idx)
{
    if (g_edge_is64) return (int)((const long long*)edge)[idx];
    return ((const int*)edge)[idx];
}

// ---------------------------------------------------------------------------
// CSR build: histogram -> block scan (3 kernels) -> counting-sort fill
// ---------------------------------------------------------------------------
__global__ void hist_kernel(const void* __restrict__ edge)
{
    int i = blockIdx.x * blockDim.x + threadIdx.x;
    if (i >= N_EDGES) return;
    atomicAdd(&g_deg[edge_at(edge, N_EDGES + i)], 1);
}

__global__ void scan1_kernel()
{
    __shared__ int s[256];
    int t = threadIdx.x, b = blockIdx.x;
    int i = b * 256 + t;
    int v = (i < N_NODES) ? g_deg[i] : 0;
    s[t] = v;
    __syncthreads();
    #pragma unroll
    for (int o = 1; o < 256; o <<= 1) {
        int add = (t >= o) ? s[t - o] : 0;
        __syncthreads();
        s[t] += add;
        __syncthreads();
    }
    if (i < N_NODES) g_incl[i] = s[t];
    if (t == 255) g_part[b] = s[255];
}

__global__ void scan2_kernel()
{
    __shared__ int s[128];
    int t = threadIdx.x;
    int v = (t < SCAN_NB) ? g_part[t] : 0;
    s[t] = v;
    __syncthreads();
    #pragma unroll
    for (int o = 1; o < 128; o <<= 1) {
        int add = (t >= o) ? s[t - o] : 0;
        __syncthreads();
        s[t] += add;
        __syncthreads();
    }
    if (t < SCAN_NB) g_partoff[t] = s[t] - v;   // exclusive prefix of block totals
}

__global__ void scan3_kernel()
{
    int i = blockIdx.x * blockDim.x + threadIdx.x;
    if (i >= N_NODES) return;
    int b = i >> 8;                              // scan1 block that covered row i
    int excl = g_incl[i] - g_deg[i] + g_partoff[b];
    g_off[i] = excl;
    g_cur[i] = excl;
    if (i == 0) g_off[N_NODES] = N_EDGES;
}

__global__ void fill_kernel(const void* __restrict__ edge)
{
    int i = blockIdx.x * blockDim.x + threadIdx.x;
    if (i >= N_EDGES) return;
    int s = edge_at(edge, i);
    int d = edge_at(edge, N_EDGES + i);
    int pos = atomicAdd(&g_cur[d], 1);
    g_csrc[pos] = s;
}

// ---------------------------------------------------------------------------
// fp32 -> bf16 hi/lo split (weights + features)
// ---------------------------------------------------------------------------
__global__ void split_kernel(const float* __restrict__ x,
                             __nv_bfloat16* __restrict__ hi,
                             __nv_bfloat16* __restrict__ lo, int n)
{
    int i = (blockIdx.x * blockDim.x + threadIdx.x) * 4;
    if (i >= n) return;
    float4 v = *(const float4*)(x + i);
    __nv_bfloat16 h0 = __float2bfloat16(v.x), h1 = __float2bfloat16(v.y);
    __nv_bfloat16 h2 = __float2bfloat16(v.z), h3 = __float2bfloat16(v.w);
    __nv_bfloat16 l0 = __float2bfloat16(v.x - __bfloat162float(h0));
    __nv_bfloat16 l1 = __float2bfloat16(v.y - __bfloat162float(h1));
    __nv_bfloat16 l2 = __float2bfloat16(v.z - __bfloat162float(h2));
    __nv_bfloat16 l3 = __float2bfloat16(v.w - __bfloat162float(h3));
    *(unsigned*)(hi + i)     = pack2(h0, h1);
    *(unsigned*)(hi + i + 2) = pack2(h2, h3);
    *(unsigned*)(lo + i)     = pack2(l0, l1);
    *(unsigned*)(lo + i + 2) = pack2(l2, l3);
}

// ---------------------------------------------------------------------------
// CSR gather + self:  out[v] = x[v] + sum_{s in N(v)} x[s],  bf16 hi/lo in/out.
// One block per node, CH threads = dim/4, float4 accumulation in registers.
// 2-edge load batching: both neighbor rows' loads issue before their adds;
// adds applied in edge order -> bit-identical to the serial loop.
// ---------------------------------------------------------------------------
__device__ __forceinline__ float4 load_hl4(const __nv_bfloat16* hi,
                                           const __nv_bfloat16* lo, size_t idx)
{
    uint2 uh = *(const uint2*)(hi + idx);
    uint2 ul = *(const uint2*)(lo + idx);
    float2 h0 = __bfloat1622float2(*(__nv_bfloat162*)&uh.x);
    float2 h1 = __bfloat1622float2(*(__nv_bfloat162*)&uh.y);
    float2 l0 = __bfloat1622float2(*(__nv_bfloat162*)&ul.x);
    float2 l1 = __bfloat1622float2(*(__nv_bfloat162*)&ul.y);
    return make_float4(h0.x + l0.x, h0.y + l0.y, h1.x + l1.x, h1.y + l1.y);
}

template <int CH>
__global__ __launch_bounds__(CH) void gather_kernel(
    const __nv_bfloat16* __restrict__ xhi, const __nv_bfloat16* __restrict__ xlo,
    __nv_bfloat16* __restrict__ ohi, __nv_bfloat16* __restrict__ olo)
{
    const int dim = CH * 4;
    const int node = blockIdx.x;
    const int t = threadIdx.x;
    const size_t base = (size_t)node * dim + t * 4;

    float4 acc = load_hl4(xhi, xlo, base);       // self term
    const int e0 = g_off[node], e1 = g_off[node + 1];
    int e = e0;
    for (; e + 1 < e1; e += 2) {
        int s0 = g_csrc[e];
        int s1 = g_csrc[e + 1];
        float4 v0 = load_hl4(xhi, xlo, (size_t)s0 * dim + t * 4);
        float4 v1 = load_hl4(xhi, xlo, (size_t)s1 * dim + t * 4);
        acc.x += v0.x; acc.y += v0.y; acc.z += v0.z; acc.w += v0.w;
        acc.x += v1.x; acc.y += v1.y; acc.z += v1.z; acc.w += v1.w;
    }
    if (e < e1) {
        int s = g_csrc[e];
        float4 v = load_hl4(xhi, xlo, (size_t)s * dim + t * 4);
        acc.x += v.x; acc.y += v.y; acc.z += v.z; acc.w += v.w;
    }

    __nv_bfloat16 h0 = __float2bfloat16(acc.x), h1 = __float2bfloat16(acc.y);
    __nv_bfloat16 h2 = __float2bfloat16(acc.z), h3 = __float2bfloat16(acc.w);
    __nv_bfloat16 l0 = __float2bfloat16(acc.x - __bfloat162float(h0));
    __nv_bfloat16 l1 = __float2bfloat16(acc.y - __bfloat162float(h1));
    __nv_bfloat16 l2 = __float2bfloat16(acc.z - __bfloat162float(h2));
    __nv_bfloat16 l3 = __float2bfloat16(acc.w - __bfloat162float(h3));
    *(unsigned*)(ohi + base)     = pack2(h0, h1);
    *(unsigned*)(ohi + base + 2) = pack2(h2, h3);
    *(unsigned*)(olo + base)     = pack2(l0, l1);
    *(unsigned*)(olo + base + 2) = pack2(l2, l3);
}

// ---------------------------------------------------------------------------
// PTX helpers + GEMM (validated R10 pipeline; OUT: 0=fp32 C, 2=bf16 hi/lo)
// ---------------------------------------------------------------------------
__device__ __forceinline__ unsigned smem_u32(const void* p)
{
    return (unsigned)__cvta_generic_to_shared(p);
}

__device__ __forceinline__ void cp16(unsigned s, const void* g, int zf)
{
    asm volatile("cp.async.cg.shared.global [%0], [%1], 16, %2;"
                 :: "r"(s), "l"(g), "r"(zf) : "memory");
}

__device__ __forceinline__ void ldsm_x4(unsigned& r0, unsigned& r1, unsigned& r2,
                                        unsigned& r3, unsigned addr)
{
    asm volatile("ldmatrix.sync.aligned.m8n8.x4.shared.b16 {%0,%1,%2,%3}, [%4];"
                 : "=r"(r0), "=r"(r1), "=r"(r2), "=r"(r3) : "r"(addr));
}

__device__ __forceinline__ void ldsm_x4t(unsigned& r0, unsigned& r1, unsigned& r2,
                                         unsigned& r3, unsigned addr)
{
    asm volatile("ldmatrix.sync.aligned.m8n8.x4.trans.shared.b16 {%0,%1,%2,%3}, [%4];"
                 : "=r"(r0), "=r"(r1), "=r"(r2), "=r"(r3) : "r"(addr));
}

__device__ __forceinline__ void mma16816(float* c, const unsigned* a, const unsigned* b)
{
    asm volatile(
        "mma.sync.aligned.m16n8k16.row.col.f32.bf16.bf16.f32 "
        "{%0,%1,%2,%3}, {%4,%5,%6,%7}, {%8,%9}, {%0,%1,%2,%3};"
        : "+f"(c[0]), "+f"(c[1]), "+f"(c[2]), "+f"(c[3])
        : "r"(a[0]), "r"(a[1]), "r"(a[2]), "r"(a[3]), "r"(b[0]), "r"(b[1]));
}

template <int ACT, int OUT>
__global__ __launch_bounds__(256) void gemm_mma_bf16(
    const __nv_bfloat16* __restrict__ Ahi, const __nv_bfloat16* __restrict__ Alo,
    const __nv_bfloat16* __restrict__ Whi, const __nv_bfloat16* __restrict__ Wlo,
    const float* __restrict__ bias,
    float* __restrict__ C,
    __nv_bfloat16* __restrict__ Chi, __nv_bfloat16* __restrict__ Clo,
    int M, int N, int K)
{
    __shared__ __align__(16) __nv_bfloat16 sAh[2][128 * 32], sAl[2][128 * 32];
    __shared__ __align__(16) __nv_bfloat16 sBh[2][32 * 64],  sBl[2][32 * 64];

    const int tid = threadIdx.x, lane = tid & 31, warp = tid >> 5;
    const int wm = warp & 3, wn = warp >> 2;
    const int row0 = blockIdx.y * 128, col0 = blockIdx.x * 64;
    const int T = K / 32;

    float acc[2][4][4];
    #pragma unroll
    for (int i = 0; i < 2; i++)
        #pragma unroll
        for (int j = 0; j < 4; j++)
            #pragma unroll
            for (int l = 0; l < 4; l++) acc[i][j][l] = 0.f;

    auto issue = [&](int t, int buf) {
        int k0 = t * 32;
        #pragma unroll
        for (int it = 0; it < 2; it++) {
            int id = tid + it * 256;
            int r = id >> 2, c = id & 3;
            int gr = row0 + r;
            int pc = c ^ ((r >> 1) & 3);
            int zf = (gr < M) ? 16 : 0;
            cp16(smem_u32(&sAh[buf][r * 32 + pc * 8]), Ahi + (size_t)gr * K + k0 + c * 8, zf);
            cp16(smem_u32(&sAl[buf][r * 32 + pc * 8]), Alo + (size_t)gr * K + k0 + c * 8, zf);
        }
        {
            int r = tid >> 3, c = tid & 7;
            int pc = c ^ (r & 7);
            cp16(smem_u32(&sBh[buf][r * 64 + pc * 8]), Whi + (size_t)(k0 + r) * N + col0 + c * 8, 16);
            cp16(smem_u32(&sBl[buf][r * 64 + pc * 8]), Wlo + (size_t)(k0 + r) * N + col0 + c * 8, 16);
        }
    };

    issue(0, 0);
    asm volatile("cp.async.commit_group;" ::: "memory");

    for (int t = 0; t < T; t++) {
        int buf = t & 1;
        if (t + 1 < T) issue(t + 1, buf ^ 1);
        asm volatile("cp.async.commit_group;" ::: "memory");
        asm volatile("cp.async.wait_group 1;" ::: "memory");
        __syncthreads();

        #pragma unroll
        for (int kt = 0; kt < 2; kt++) {
            unsigned ah[2][4], al[2][4], bh[2][4], bl[2][4];
            #pragma unroll
            for (int mi = 0; mi < 2; mi++) {
                int rr = wm * 32 + mi * 16 + (lane & 15);
                int cc = kt * 2 + (lane >> 4);
                int pc = cc ^ ((rr >> 1) & 3);
                ldsm_x4(ah[mi][0], ah[mi][1], ah[mi][2], ah[mi][3],
                        smem_u32(&sAh[buf][rr * 32 + pc * 8]));
                ldsm_x4(al[mi][0], al[mi][1], al[mi][2], al[mi][3],
                        smem_u32(&sAl[buf][rr * 32 + pc * 8]));
            }
            #pragma unroll
            for (int nb = 0; nb < 2; nb++) {
                int kk = kt * 16 + (lane & 15);
                int cc = wn * 4 + nb * 2 + (lane >> 4);
                int pc = cc ^ (kk & 7);
                ldsm_x4t(bh[nb][0], bh[nb][1], bh[nb][2], bh[nb][3],
                         smem_u32(&sBh[buf][kk * 64 + pc * 8]));
                ldsm_x4t(bl[nb][0], bl[nb][1], bl[nb][2], bl[nb][3],
                         smem_u32(&sBl[buf][kk * 64 + pc * 8]));
            }
            #pragma unroll
            for (int mi = 0; mi < 2; mi++)
                #pragma unroll
                for (int ni = 0; ni < 4; ni++) {
                    const unsigned* qh = &bh[ni >> 1][(ni & 1) * 2];
                    const unsigned* ql = &bl[ni >> 1][(ni & 1) * 2];
                    mma16816(acc[mi][ni], ah[mi], qh);
                    mma16816(acc[mi][ni], al[mi], qh);
                    mma16816(acc[mi][ni], ah[mi], ql);
                }
        }
        __syncthreads();
    }

    const int gid = lane >> 2, tig = lane & 3;
    #pragma unroll
    for (int ni = 0; ni < 4; ni++) {
        int cn = col0 + wn * 32 + ni * 8 + tig * 2;
        float2 bv = *(const float2*)(bias + cn);
        #pragma unroll
        for (int mi = 0; mi < 2; mi++) {
            #pragma unroll
            for (int h = 0; h < 2; h++) {
                int gr = row0 + wm * 32 + mi * 16 + gid + h * 8;
                if (gr < M) {
                    float z0 = acc[mi][ni][h * 2 + 0] + bv.x;
                    float z1 = acc[mi][ni][h * 2 + 1] + bv.y;
                    float o0 = (ACT == 2) ? elu2(z0) : (ACT == 1 ? elu1(z0) : z0);
                    float o1 = (ACT == 2) ? elu2(z1) : (ACT == 1 ? elu1(z1) : z1);
                    size_t off = (size_t)gr * N + cn;
                    if (OUT == 2) {
                        __nv_bfloat16 h0 = __float2bfloat16(o0);
                        __nv_bfloat16 h1 = __float2bfloat16(o1);
                        __nv_bfloat16 l0 = __float2bfloat16(o0 - __bfloat162float(h0));
                        __nv_bfloat16 l1 = __float2bfloat16(o1 - __bfloat162float(h1));
                        *(unsigned*)(Chi + off) = pack2(h0, h1);
                        *(unsigned*)(Clo + off) = pack2(l0, l1);
                    } else {
                        float2 o; o.x = o0; o.y = o1;
                        *(float2*)(C + off) = o;
                    }
                }
            }
        }
    }
}

// ---------------------------------------------------------------------------
static inline dim3 gemm_grid(int M, int N) { return dim3(N / 64, (M + 127) / 128); }
static inline int  split_grid(int n)       { return (n / 4 + 255) / 256; }

extern "C" void kernel_launch(void* const* d_in, const int* in_sizes, int n_in,
                              void* d_out, int out_size)
{
    const float* features = (const float*)d_in[0];
    const void*  edge     = d_in[1];
    const float* w1a = (const float*)d_in[2];
    const float* b1a = (const float*)d_in[3];
    const float* w1b = (const float*)d_in[4];
    const float* b1b = (const float*)d_in[5];
    const float* w2a = (const float*)d_in[6];
    const float* b2a = (const float*)d_in[7];
    const float* w2b = (const float*)d_in[8];
    const float* b2b = (const float*)d_in[9];
    const float* w3a = (const float*)d_in[10];
    const float* b3a = (const float*)d_in[11];
    const float* w3b = (const float*)d_in[12];
    const float* b3b = (const float*)d_in[13];
    const float* wr  = (const float*)d_in[14];
    const float* br  = (const float*)d_in[15];

    float* out_x   = (float*)d_out;
    float* out_res = out_x + (size_t)N_NODES * 256;

    __nv_bfloat16 *fhi, *flo, *ahi, *alo, *hhi, *hlo, *xhi, *xlo, *whi, *wlo;
    int* degp;
    cudaGetSymbolAddress((void**)&fhi, g_fhi);
    cudaGetSymbolAddress((void**)&flo, g_flo);
    cudaGetSymbolAddress((void**)&ahi, g_ahi);
    cudaGetSymbolAddress((void**)&alo, g_alo);
    cudaGetSymbolAddress((void**)&hhi, g_hhi);
    cudaGetSymbolAddress((void**)&hlo, g_hlo);
    cudaGetSymbolAddress((void**)&xhi, g_xhi);
    cudaGetSymbolAddress((void**)&xlo, g_xlo);
    cudaGetSymbolAddress((void**)&whi, g_whi);
    cudaGetSymbolAddress((void**)&wlo, g_wlo);
    cudaGetSymbolAddress((void**)&degp, g_deg);

    detect_dtype_kernel<<<1, 256>>>(edge);

    // ---- CSR build (once; shared by all 3 aggregations) ----
    cudaMemsetAsync(degp, 0, N_NODES * sizeof(int));
    hist_kernel<<<(N_EDGES + 255) / 256, 256>>>(edge);
    scan1_kernel<<<SCAN_NB, 256>>>();
    scan2_kernel<<<1, 128>>>();
    scan3_kernel<<<SCAN_NB, 256>>>();
    fill_kernel<<<(N_EDGES + 255) / 256, 256>>>(edge);

    // ---- weight + feature splits ----
    split_kernel<<<split_grid(256 * 640), 256>>>(w1a, whi + OFF_W1A, wlo + OFF_W1A, 256 * 640);
    split_kernel<<<split_grid(640 * 640), 256>>>(w1b, whi + OFF_W1B, wlo + OFF_W1B, 640 * 640);
    split_kernel<<<split_grid(640 * 320), 256>>>(w2a, whi + OFF_W2A, wlo + OFF_W2A, 640 * 320);
    split_kernel<<<split_grid(320 * 320), 256>>>(w2b, whi + OFF_W2B, wlo + OFF_W2B, 320 * 320);
    split_kernel<<<split_grid(320 * 256), 256>>>(w3a, whi + OFF_W3A, wlo + OFF_W3A, 320 * 256);
    split_kernel<<<split_grid(256 * 256), 256>>>(w3b, whi + OFF_W3B, wlo + OFF_W3B, 256 * 256);
    split_kernel<<<split_grid(256 * 256), 256>>>(wr,  whi + OFF_WR,  wlo + OFF_WR,  256 * 256);
    split_kernel<<<split_grid(N_NODES * 256), 256>>>(features, fhi, flo, N_NODES * 256);

    // residual: res = elu(features @ wr + br)
    gemm_mma_bf16<1, 0><<<gemm_grid(N_NODES, 256), 256>>>(
        fhi, flo, whi + OFF_WR, wlo + OFF_WR, br,
        out_res, nullptr, nullptr, N_NODES, 256, 256);

    // ---- layer 1 (256 -> 640) ----
    gather_kernel<64><<<N_NODES, 64>>>(fhi, flo, ahi, alo);
    gemm_mma_bf16<1, 2><<<gemm_grid(N_NODES, 640), 256>>>(
        ahi, alo, whi + OFF_W1A, wlo + OFF_W1A, b1a,
        nullptr, hhi, hlo, N_NODES, 640, 256);
    gemm_mma_bf16<2, 2><<<gemm_grid(N_NODES, 640), 256>>>(
        hhi, hlo, whi + OFF_W1B, wlo + OFF_W1B, b1b,
        nullptr, xhi, xlo, N_NODES, 640, 640);

    // ---- layer 2 (640 -> 320) ----
    gather_kernel<160><<<N_NODES, 160>>>(xhi, xlo, ahi, alo);
    gemm_mma_bf16<1, 2><<<gemm_grid(N_NODES, 320), 256>>>(
        ahi, alo, whi + OFF_W2A, wlo + OFF_W2A, b2a,
        nullptr, hhi, hlo, N_NODES, 320, 640);
    gemm_mma_bf16<2, 2><<<gemm_grid(N_NODES, 320), 256>>>(
        hhi, hlo, whi + OFF_W2B, wlo + OFF_W2B, b2b,
        nullptr, xhi, xlo, N_NODES, 320, 320);

    // ---- layer 3 (320 -> 256), no outer elu ----
    gather_kernel<80><<<N_NODES, 80>>>(xhi, xlo, ahi, alo);
    gemm_mma_bf16<1, 2><<<gemm_grid(N_NODES, 256), 256>>>(
        ahi, alo, whi + OFF_W3A, wlo + OFF_W3A, b3a,
        nullptr, hhi, hlo, N_NODES, 256, 320);
    gemm_mma_bf16<1, 0><<<gemm_grid(N_NODES, 256), 256>>>(
        hhi, hlo, whi + OFF_W3B, wlo + OFF_W3B, b3b,
        out_x, nullptr, nullptr, N_NODES, 256, 256);
}